// round 2
// baseline (speedup 1.0000x reference)
#include <cuda_runtime.h>
#include <cuda_bf16.h>
#include <math.h>
#include <stdint.h>

#define BSZ 256
#define D   512
#define KC  64
#define NKC (D/KC)
#define HALF 128
#define SROW 72            // padded bf16 row (144 B) for operand tiles -> conflict-free frag LDS
#define GROW 257           // padded float row for G tile (column access conflict-free)
#define NEG (-1.0e30f)

// --- device scratch (no allocations allowed) ---
__device__ __nv_bfloat16 g_Yb[BSZ*D];
__device__ float g_px_m[BSZ*BSZ];   // [s][a]  anchor-x partials
__device__ float g_px_s[BSZ*BSZ];
__device__ float g_py_m[BSZ*BSZ];   // [s][r]  anchor-y partials
__device__ float g_py_s[BSZ*BSZ];
__device__ float g_lse_z[BSZ];      // anchor-z final LSE per s

// --- dynamic smem layout ---
#define YS_OFF   (HALF*SROW*2)            /* 18432: Ws occupies [0, YS_OFF) */
#define G_BYTES  (HALF*GROW*4)            /* 131584 (union with Ws+Ys)      */
#define COLM_OFF G_BYTES
#define COLS_OFF (COLM_OFF + BSZ*4)
#define ROWM_OFF (COLS_OFF + BSZ*4)
#define ROWS_OFF (ROWM_OFF + HALF*4)
#define PLANE_OFF (ROWS_OFF + HALF*4)
#define SMEM_BYTES (PLANE_OFF + 16)       /* ~134688 B */

__device__ __forceinline__ void lse_merge(float& M, float& S, float m2, float s2){
    if (m2 > M){ S = S * __expf(M - m2) + s2; M = m2; }
    else       { S = S + s2 * __expf(m2 - M); }
}

__global__ void conv_y_kernel(const float* __restrict__ Y){
    int i = blockIdx.x * blockDim.x + threadIdx.x;
    g_Yb[i] = __float2bfloat16(Y[i]);
}

__global__ void __launch_bounds__(512, 1)
symile_main(const float* __restrict__ X, const float* __restrict__ Z){
    extern __shared__ char smem[];
    __nv_bfloat16* Ws = (__nv_bfloat16*)(smem);
    __nv_bfloat16* Ys = (__nv_bfloat16*)(smem + YS_OFF);
    float* G    = (float*)smem;                 // union: reused after GEMM
    float* colM = (float*)(smem + COLM_OFF);
    float* colS = (float*)(smem + COLS_OFF);
    float* rowM = (float*)(smem + ROWM_OFF);
    float* rowS = (float*)(smem + ROWS_OFF);
    float* plane= (float*)(smem + PLANE_OFF);

    const int tid  = threadIdx.x;
    const int s    = blockIdx.x;
    const int warp = tid >> 5, lane = tid & 31;
    const int g    = lane >> 2, tg = lane & 3;
    const int wm   = warp & 3, wn = warp >> 2;   // 4x4 warp grid: 32-row x 64-col tiles

    if (tid < BSZ){ colM[tid] = NEG; colS[tid] = 0.f; }
    if (tid == 0){ plane[0] = NEG; plane[1] = 0.f; }

    for (int half = 0; half < 2; ++half){
        const int aBase = half * HALF;
        float c[2][8][4];
        #pragma unroll
        for (int mt = 0; mt < 2; ++mt)
            #pragma unroll
            for (int nt = 0; nt < 8; ++nt)
                #pragma unroll
                for (int i = 0; i < 4; ++i) c[mt][nt][i] = 0.f;

        for (int kc = 0; kc < NKC; ++kc){
            const int k0 = kc * KC;
            __syncthreads();   // smem (Ws/Ys/G union) free for reuse
            // W = x .* z[s]  (fp32 product, single bf16 rounding), 128 x 64
            #pragma unroll
            for (int e = tid; e < HALF*KC/4; e += 512){
                int row = e >> 4, q = e & 15;
                const float4 xv = *(const float4*)(X + (aBase+row)*D + k0 + q*4);
                const float4 zv = *(const float4*)(Z + s*D + k0 + q*4);
                __nv_bfloat162 p0 = __floats2bfloat162_rn(xv.x*zv.x, xv.y*zv.y);
                __nv_bfloat162 p1 = __floats2bfloat162_rn(xv.z*zv.z, xv.w*zv.w);
                *(__nv_bfloat162*)(Ws + row*SROW + q*4)     = p0;
                *(__nv_bfloat162*)(Ws + row*SROW + q*4 + 2) = p1;
            }
            // Y chunk, 256 x 64 bf16
            #pragma unroll
            for (int e = tid; e < BSZ*KC/4; e += 512){
                int row = e >> 4, q = e & 15;
                *(uint2*)(Ys + row*SROW + q*4) = *(const uint2*)(g_Yb + row*D + k0 + q*4);
            }
            __syncthreads();
            #pragma unroll
            for (int ks = 0; ks < 4; ++ks){
                const int kk = ks * 16;
                unsigned a[2][4];
                #pragma unroll
                for (int mt = 0; mt < 2; ++mt){
                    int ar = (wm*32 + mt*16 + g)*SROW + kk + tg*2;
                    a[mt][0] = *(const unsigned*)(Ws + ar);
                    a[mt][1] = *(const unsigned*)(Ws + ar + 8*SROW);
                    a[mt][2] = *(const unsigned*)(Ws + ar + 8);
                    a[mt][3] = *(const unsigned*)(Ws + ar + 8*SROW + 8);
                }
                unsigned b[8][2];
                #pragma unroll
                for (int nt = 0; nt < 8; ++nt){
                    int br = (wn*64 + nt*8 + g)*SROW + kk + tg*2;
                    b[nt][0] = *(const unsigned*)(Ys + br);
                    b[nt][1] = *(const unsigned*)(Ys + br + 8);
                }
                #pragma unroll
                for (int mt = 0; mt < 2; ++mt)
                    #pragma unroll
                    for (int nt = 0; nt < 8; ++nt)
                        asm volatile(
                          "mma.sync.aligned.m16n8k16.row.col.f32.bf16.bf16.f32 "
                          "{%0,%1,%2,%3}, {%4,%5,%6,%7}, {%8,%9}, {%0,%1,%2,%3};\n"
                          : "+f"(c[mt][nt][0]), "+f"(c[mt][nt][1]),
                            "+f"(c[mt][nt][2]), "+f"(c[mt][nt][3])
                          : "r"(a[mt][0]), "r"(a[mt][1]), "r"(a[mt][2]), "r"(a[mt][3]),
                            "r"(b[nt][0]), "r"(b[nt][1]));
            }
        }
        __syncthreads();   // all mma operand reads done; Ws/Ys may be overwritten by G
        // spill accumulators: G[128][256] for this half
        #pragma unroll
        for (int mt = 0; mt < 2; ++mt)
            #pragma unroll
            for (int nt = 0; nt < 8; ++nt){
                int row = wm*32 + mt*16 + g;
                int col = wn*64 + nt*8 + tg*2;
                G[row*GROW + col]         = c[mt][nt][0];
                G[row*GROW + col + 1]     = c[mt][nt][1];
                G[(row+8)*GROW + col]     = c[mt][nt][2];
                G[(row+8)*GROW + col + 1] = c[mt][nt][3];
            }
        __syncthreads();

        // ---- row reduce: per-a LSE partial over r (anchor-x) ----
        {
            int row = tid >> 2, part = tid & 3;
            const float* Gr = G + row*GROW + part*64;
            float m = NEG;
            #pragma unroll 8
            for (int cc = 0; cc < 64; ++cc) m = fmaxf(m, Gr[cc]);
            m = fmaxf(m, __shfl_xor_sync(0xffffffffu, m, 1));
            m = fmaxf(m, __shfl_xor_sync(0xffffffffu, m, 2));
            float sum = 0.f;
            #pragma unroll 8
            for (int cc = 0; cc < 64; ++cc) sum += __expf(Gr[cc] - m);
            sum += __shfl_xor_sync(0xffffffffu, sum, 1);
            sum += __shfl_xor_sync(0xffffffffu, sum, 2);
            if (part == 0){
                int a_glob = aBase + row;
                g_px_m[s*BSZ + a_glob] = m;
                g_px_s[s*BSZ + a_glob] = sum;
                rowM[row] = m; rowS[row] = sum;
            }
        }
        // ---- col reduce: per-r LSE partial over a (anchor-y), running across halves ----
        {
            int col = tid >> 1, part = tid & 1;
            const float* Gc = G + part*64*GROW + col;
            float m = NEG;
            #pragma unroll 8
            for (int rr = 0; rr < 64; ++rr) m = fmaxf(m, Gc[rr*GROW]);
            m = fmaxf(m, __shfl_xor_sync(0xffffffffu, m, 1));
            float sum = 0.f;
            #pragma unroll 8
            for (int rr = 0; rr < 64; ++rr) sum += __expf(Gc[rr*GROW] - m);
            sum += __shfl_xor_sync(0xffffffffu, sum, 1);
            if (part == 0) lse_merge(colM[col], colS[col], m, sum);
        }
        __syncthreads();   // rowM/rowS visible to warp 0
        // ---- plane reduce (anchor-z): merge 128 row partials ----
        if (warp == 0){
            float M = NEG, S = 0.f;
            #pragma unroll
            for (int j = 0; j < 4; ++j) lse_merge(M, S, rowM[lane + j*32], rowS[lane + j*32]);
            #pragma unroll
            for (int off = 16; off > 0; off >>= 1){
                float m2 = __shfl_xor_sync(0xffffffffu, M, off);
                float s2 = __shfl_xor_sync(0xffffffffu, S, off);
                lse_merge(M, S, m2, s2);
            }
            if (lane == 0) lse_merge(plane[0], plane[1], M, S);
        }
        __syncthreads();   // plane done; G region free for next half's operands
    }
    if (tid < BSZ){
        g_py_m[s*BSZ + tid] = colM[tid];
        g_py_s[s*BSZ + tid] = colS[tid];
    }
    if (tid == 0) g_lse_z[s] = plane[0] + logf(plane[1]);
}

__global__ void symile_finalize(const float* __restrict__ X, const float* __restrict__ Y,
                                const float* __restrict__ Z, float* __restrict__ out){
    __shared__ float red[BSZ];
    const int t = threadIdx.x;
    float M = NEG, S = 0.f;
    for (int si = 0; si < BSZ; ++si)
        lse_merge(M, S, g_px_m[si*BSZ + t], g_px_s[si*BSZ + t]);
    const float lx = M + logf(S);
    M = NEG; S = 0.f;
    for (int si = 0; si < BSZ; ++si)
        lse_merge(M, S, g_py_m[si*BSZ + t], g_py_s[si*BSZ + t]);
    const float ly = M + logf(S);
    const float lz = g_lse_z[t];
    float diag = 0.f;
    for (int dd = 0; dd < D; dd += 4){
        float4 xv = *(const float4*)(X + t*D + dd);
        float4 yv = *(const float4*)(Y + t*D + dd);
        float4 zv = *(const float4*)(Z + t*D + dd);
        diag += xv.x*yv.x*zv.x + xv.y*yv.y*zv.y + xv.z*yv.z*zv.z + xv.w*yv.w*zv.w;
    }
    red[t] = lx + ly + lz - 3.f*diag;
    __syncthreads();
    for (int off = 128; off > 0; off >>= 1){
        if (t < off) red[t] += red[t + off];
        __syncthreads();
    }
    if (t == 0) out[0] = red[0] / 768.f;   // (1/3) * (1/256) * sum of three per-line losses
}

extern "C" void kernel_launch(void* const* d_in, const int* in_sizes, int n_in,
                              void* d_out, int out_size){
    const float* X = (const float*)d_in[0];
    const float* Y = (const float*)d_in[1];
    const float* Z = (const float*)d_in[2];
    float* out = (float*)d_out;

    cudaFuncSetAttribute(symile_main, cudaFuncAttributeMaxDynamicSharedMemorySize, SMEM_BYTES);

    conv_y_kernel<<<(BSZ*D)/256, 256>>>(Y);
    symile_main<<<BSZ, 512, SMEM_BYTES>>>(X, Z);
    symile_finalize<<<1, BSZ>>>(X, Y, Z, out);
}